// round 8
// baseline (speedup 1.0000x reference)
#include <cuda_runtime.h>
#include <cstdint>

#define NSEG   10000
#define NROWS  500000
#define D      128
#define BM     72
#define BLK_B  576
#define TBLK   16
#define RPB    64                         // rows per sum block
#define NBLK_S ((NROWS + RPB - 1) / RPB)  // 7813
#define XS_STRIDE 132
#define SMEM_B ((D * D + BM * XS_STRIDE) * 4)   // 103552 bytes

__device__ float g_sums[NSEG * D];
__device__ float g_WT[D * D];     // g_WT[k*D + n] = W[n*D + k]

// graph may be int32 or int64 depending on jax x64 config.
// int32 layout: word[2*NSEG-1] = ends[NSEG-1] = N-1 (nonzero).
// int64 layout: word[2*NSEG-1] = high half of element NSEG-1 -> 0.
__device__ __forceinline__ bool graph_is64(const int* __restrict__ g) {
    return g[2 * NSEG - 1] == 0;
}
__device__ __forceinline__ int seg_start(const int* __restrict__ g, bool is64, int s) {
    return is64 ? g[4 * s] : g[2 * s];           // low word (values < 2^31)
}
__device__ __forceinline__ int seg_end(const int* __restrict__ g, bool is64, int s) {
    return is64 ? g[4 * s + 2] : g[2 * s + 1];
}
__device__ __forceinline__ void load_seg(const int* __restrict__ g, int s,
                                         int& st, int& en) {
    bool is64 = graph_is64(g);
    st = seg_start(g, is64, s);
    en = seg_end(g, is64, s);
}

// ---------------------------------------------------------------------------
// Kernel 1: blocks [0,TBLK) transpose W into g_WT. Blocks [TBLK,...):
// ROW-PARTITIONED sum. Block owns rows [blk*RPB, blk*RPB+RPB): binary-search
// the first segment, then walk runs; per run accumulate in regs (4-deep
// LDG.128 pipeline), cross-warp reduce in smem, RED.ADD.F32 into g_sums
// (pre-zeroed by a memset node). Perfect load balance, pure streaming.
// ---------------------------------------------------------------------------
__global__ void __launch_bounds__(128) sum_kernel(
    const float* __restrict__ input,
    const int*   __restrict__ graph,
    const float* __restrict__ W)
{
    if (blockIdx.x < TBLK) {
        int base = blockIdx.x * (D * D / TBLK);          // 1024 elems/block
#pragma unroll
        for (int i = 0; i < (D * D / TBLK) / 128; i++) { // 8 iters
            int lin = base + threadIdx.x + i * 128;
            int k = lin >> 7;
            int n = lin & 127;
            g_WT[lin] = W[n * D + k];
        }
        return;
    }

    const int blk = blockIdx.x - TBLK;
    const int r0  = blk * RPB;
    const int r1  = min(r0 + RPB, NROWS);      // exclusive
    const int c4  = threadIdx.x & 31;          // float4 column
    const int rl  = threadIdx.x >> 5;          // warp id 0..3

    const bool is64 = graph_is64(graph);

    // Binary search: largest seg with start[seg] <= r0. All threads redundant
    // (broadcast loads, graph is L2-resident).
    int lo = 0, hi = NSEG - 1;
    while (lo < hi) {
        int mid = (lo + hi + 1) >> 1;
        if (seg_start(graph, is64, mid) <= r0) lo = mid; else hi = mid - 1;
    }

    __shared__ float4 red[4][32];

    int seg = lo;
    int r   = r0;
    while (r < r1) {
        int en   = seg_end(graph, is64, seg);   // inclusive
        int stop = min(en, r1 - 1);
        int len  = stop - r + 1;

        const float4* base = (const float4*)input + (long long)r * 32 + c4;

        float4 acc = make_float4(0.f, 0.f, 0.f, 0.f);
        int i = rl;
        for (; i + 12 < len; i += 16) {
            const float4* p = base + (long long)i * 32;
            float4 v0 = p[0 * 32];
            float4 v1 = p[4 * 32];
            float4 v2 = p[8 * 32];
            float4 v3 = p[12 * 32];
            acc.x += (v0.x + v1.x) + (v2.x + v3.x);
            acc.y += (v0.y + v1.y) + (v2.y + v3.y);
            acc.z += (v0.z + v1.z) + (v2.z + v3.z);
            acc.w += (v0.w + v1.w) + (v2.w + v3.w);
        }
        for (; i < len; i += 4) {
            float4 v = base[(long long)i * 32];
            acc.x += v.x; acc.y += v.y; acc.z += v.z; acc.w += v.w;
        }

        red[rl][c4] = acc;
        __syncthreads();
        if (rl == 0) {
            float4 a = red[0][c4], b2 = red[1][c4], c = red[2][c4], d = red[3][c4];
            float* dst = g_sums + seg * D + c4 * 4;
            atomicAdd(dst + 0, (a.x + b2.x) + (c.x + d.x));
            atomicAdd(dst + 1, (a.y + b2.y) + (c.y + d.y));
            atomicAdd(dst + 2, (a.z + b2.z) + (c.z + d.z));
            atomicAdd(dst + 3, (a.w + b2.w) + (c.w + d.w));
        }
        __syncthreads();

        r = stop + 1;
        seg++;
    }
}

// ---------------------------------------------------------------------------
// Kernel 2: out[m][n] = sum_k xs[m][k] * WT[k][n] + cnt_m * b[n]
// (UNCHANGED from R7 — protected.) BM=72/block, 576 threads -> 139 blocks =
// ONE wave, 18 warps/SM. Thread = 2m x 8n, conflict-free W reads.
// ---------------------------------------------------------------------------
__global__ void __launch_bounds__(BLK_B) seg_gemm_kernel(
    const int*   __restrict__ graph,
    const float* __restrict__ b,
    float*       __restrict__ out)
{
    extern __shared__ float sm[];
    float* ws = sm;            // ws[k*D + n]  (64KB copy of g_WT)
    float* xs = sm + D * D;    // xs[m*XS_STRIDE + k]

    const int tid = threadIdx.x;
    const int m0  = blockIdx.x * BM;

    {
        const float4* src = (const float4*)g_WT;
        for (int lin = tid; lin < D * D / 4; lin += BLK_B)
            ((float4*)ws)[lin] = src[lin];
    }
    {
#pragma unroll
        for (int i = 0; i < (BM * D / 4) / BLK_B; i++) {   // 4 iters
            int lin = tid + i * BLK_B;
            int m   = lin >> 5;
            int k4  = lin & 31;
            int seg = m0 + m;
            float4 v = make_float4(0.f, 0.f, 0.f, 0.f);
            if (seg < NSEG) v = ((const float4*)g_sums)[seg * 32 + k4];
            *(float4*)(xs + m * XS_STRIDE + k4 * 4) = v;
        }
    }
    __syncthreads();

    const int tx = tid & 15;    // n-groups: [tx*4, +4) and [64+tx*4, +4)
    const int ty = tid >> 4;    // m-group: m = ty*2, ty*2+1  (ty 0..35)

    float acc[2][8];
#pragma unroll
    for (int i = 0; i < 2; i++)
#pragma unroll
        for (int j = 0; j < 8; j++) acc[i][j] = 0.f;

    const float* xp0 = xs + (ty * 2 + 0) * XS_STRIDE;
    const float* xp1 = xs + (ty * 2 + 1) * XS_STRIDE;
    const float* wp  = ws + tx * 4;

#pragma unroll 2
    for (int k = 0; k < D; k += 4) {
        float4 xv0 = *(const float4*)(xp0 + k);
        float4 xv1 = *(const float4*)(xp1 + k);
        const float xr[2][4] = {
            {xv0.x, xv0.y, xv0.z, xv0.w},
            {xv1.x, xv1.y, xv1.z, xv1.w},
        };
#pragma unroll
        for (int kk = 0; kk < 4; kk++) {
            float4 w0 = *(const float4*)(wp + (k + kk) * D);
            float4 w1 = *(const float4*)(wp + (k + kk) * D + 64);
#pragma unroll
            for (int i = 0; i < 2; i++) {
                float x = xr[i][kk];
                acc[i][0] += x * w0.x; acc[i][1] += x * w0.y;
                acc[i][2] += x * w0.z; acc[i][3] += x * w0.w;
                acc[i][4] += x * w1.x; acc[i][5] += x * w1.y;
                acc[i][6] += x * w1.z; acc[i][7] += x * w1.w;
            }
        }
    }

    float4 b0 = ((const float4*)b)[tx];
    float4 b1 = ((const float4*)b)[16 + tx];

#pragma unroll
    for (int i = 0; i < 2; i++) {
        int seg = m0 + ty * 2 + i;
        if (seg >= NSEG) continue;
        int st, en;
        load_seg(graph, seg, st, en);
        float cnt = (float)(en - st + 1);

        float4 o0, o1;
        o0.x = acc[i][0] + cnt * b0.x;
        o0.y = acc[i][1] + cnt * b0.y;
        o0.z = acc[i][2] + cnt * b0.z;
        o0.w = acc[i][3] + cnt * b0.w;
        o1.x = acc[i][4] + cnt * b1.x;
        o1.y = acc[i][5] + cnt * b1.y;
        o1.z = acc[i][6] + cnt * b1.z;
        o1.w = acc[i][7] + cnt * b1.w;

        float* op = out + (long long)seg * D;
        *(float4*)(op + tx * 4)      = o0;
        *(float4*)(op + 64 + tx * 4) = o1;
    }
}

extern "C" void kernel_launch(void* const* d_in, const int* in_sizes, int n_in,
                              void* d_out, int out_size) {
    const float* input = (const float*)d_in[0];
    const int*   graph = (const int*)  d_in[1];
    const float* W     = (const float*)d_in[2];
    const float* b     = (const float*)d_in[3];
    float*       out   = (float*)d_out;

    cudaFuncSetAttribute(seg_gemm_kernel,
                         cudaFuncAttributeMaxDynamicSharedMemorySize, SMEM_B);

    // Zero the accumulator (memset node, ~0.7us), then sum, then gemm.
    void* sums_ptr = nullptr;
    cudaGetSymbolAddress(&sums_ptr, g_sums);
    cudaMemsetAsync(sums_ptr, 0, (size_t)NSEG * D * sizeof(float));

    sum_kernel<<<TBLK + NBLK_S, 128>>>(input, graph, W);
    seg_gemm_kernel<<<(NSEG + BM - 1) / BM, BLK_B, SMEM_B>>>(graph, b, out);
}

// round 9
// speedup vs baseline: 1.0004x; 1.0004x over previous
#include <cuda_runtime.h>
#include <cstdint>

#define NSEG   10000
#define NROWS  500000
#define D      128
#define BM     72
#define BLK_B  576
#define BLK_S  576
#define NWARP  (BLK_S / 32)               // 18
#define TBLK   16
#define NBLK_G ((NSEG + BM - 1) / BM)     // 139
#define XS_STRIDE 132
#define SMEM_B ((D * D + BM * XS_STRIDE) * 4)   // 103552 bytes

__device__ float g_sums[NSEG * D];
__device__ float g_WT[D * D];     // g_WT[k*D + n] = W[n*D + k]

// graph may be int32 or int64 depending on jax x64 config.
// int32 layout: word[2*NSEG-1] = ends[NSEG-1] = N-1 (nonzero).
// int64 layout: word[2*NSEG-1] = high half of element NSEG-1 -> 0.
__device__ __forceinline__ bool graph_is64(const int* __restrict__ g) {
    return g[2 * NSEG - 1] == 0;
}
__device__ __forceinline__ int seg_start(const int* __restrict__ g, bool is64, int s) {
    return is64 ? g[4 * s] : g[2 * s];
}
__device__ __forceinline__ int seg_end(const int* __restrict__ g, bool is64, int s) {
    return is64 ? g[4 * s + 2] : g[2 * s + 1];
}

// ---------------------------------------------------------------------------
// Kernel 1: blocks [0,TBLK): transpose W -> g_WT (hidden under streaming).
// Blocks [TBLK,...): gemm-tile-aligned sum. Block owns segs [m0,m0+72);
// its contiguous row range is split into 18 equal per-warp chunks. Each warp
// streams its chunk with unroll-8 LDG.128, flushing per-segment register
// accumulators: STG.128 if the segment is wholly inside the chunk, scalar
// atomicAdd (into pre-zeroed g_sums) for chunk-boundary segments.
// ---------------------------------------------------------------------------
__global__ void __launch_bounds__(BLK_S) sum_kernel(
    const float* __restrict__ input,
    const int*   __restrict__ graph,
    const float* __restrict__ W)
{
    const int tid = threadIdx.x;

    if (blockIdx.x < TBLK) {
        int base = blockIdx.x * (D * D / TBLK);          // 1024 elems/block
        for (int lin = base + tid; lin < base + D * D / TBLK; lin += BLK_S) {
            int k = lin >> 7;
            int n = lin & 127;
            g_WT[lin] = W[n * D + k];
        }
        return;
    }

    const int blk = blockIdx.x - TBLK;
    const int m0  = blk * BM;
    const int s1  = min(m0 + BM, NSEG);
    const int ns  = s1 - m0;

    __shared__ int sst[BM];
    __shared__ int sen[BM];
    {
        const bool is64 = graph_is64(graph);
        for (int i = tid; i < ns; i += BLK_S) {
            sst[i] = seg_start(graph, is64, m0 + i);
            sen[i] = seg_end(graph, is64, m0 + i);
        }
    }
    __syncthreads();

    const int R0 = sst[0];
    const int R1 = sen[ns - 1] + 1;            // exclusive
    const int total = R1 - R0;
    const int ck = (total + NWARP - 1) / NWARP;

    const int warp = tid >> 5;
    const int lane = tid & 31;

    const int a   = R0 + warp * ck;
    const int bnd = min(a + ck, R1);
    if (a >= bnd) return;                      // no syncthreads after this

    // Find seg containing row a (binary search over smem table).
    int lo = 0, hi = ns - 1;
    while (lo < hi) {
        int mid = (lo + hi + 1) >> 1;
        if (sst[mid] <= a) lo = mid; else hi = mid - 1;
    }
    int seg = lo;

    int r = a;
    while (r < bnd) {
        const int e   = min(sen[seg] + 1, bnd);
        const int len = e - r;

        const float4* p = (const float4*)input + (long long)r * 32 + lane;
        float4 acc = make_float4(0.f, 0.f, 0.f, 0.f);

        int i = 0;
        for (; i + 8 <= len; i += 8) {
            float4 v0 = p[0 * 32], v1 = p[1 * 32], v2 = p[2 * 32], v3 = p[3 * 32];
            float4 v4 = p[4 * 32], v5 = p[5 * 32], v6 = p[6 * 32], v7 = p[7 * 32];
            acc.x += ((v0.x + v1.x) + (v2.x + v3.x)) + ((v4.x + v5.x) + (v6.x + v7.x));
            acc.y += ((v0.y + v1.y) + (v2.y + v3.y)) + ((v4.y + v5.y) + (v6.y + v7.y));
            acc.z += ((v0.z + v1.z) + (v2.z + v3.z)) + ((v4.z + v5.z) + (v6.z + v7.z));
            acc.w += ((v0.w + v1.w) + (v2.w + v3.w)) + ((v4.w + v5.w) + (v6.w + v7.w));
            p += 8 * 32;
        }
        for (; i < len; i++) {
            float4 v = p[0];
            acc.x += v.x; acc.y += v.y; acc.z += v.z; acc.w += v.w;
            p += 32;
        }

        // Flush this segment's partial.
        const bool excl = (sst[seg] >= a) && (sen[seg] < bnd);
        float* dst = g_sums + (long long)(m0 + seg) * D + lane * 4;
        if (excl) {
            *(float4*)dst = acc;
        } else {
            atomicAdd(dst + 0, acc.x);
            atomicAdd(dst + 1, acc.y);
            atomicAdd(dst + 2, acc.z);
            atomicAdd(dst + 3, acc.w);
        }

        r = e;
        seg++;
    }
}

// ---------------------------------------------------------------------------
// Kernel 2: out[m][n] = sum_k xs[m][k] * WT[k][n] + cnt_m * b[n]
// (UNCHANGED from R7 — protected.) BM=72/block, 576 threads -> 139 blocks =
// ONE wave, 18 warps/SM. Thread = 2m x 8n, conflict-free W reads.
// ---------------------------------------------------------------------------
__global__ void __launch_bounds__(BLK_B) seg_gemm_kernel(
    const int*   __restrict__ graph,
    const float* __restrict__ b,
    float*       __restrict__ out)
{
    extern __shared__ float sm[];
    float* ws = sm;            // ws[k*D + n]  (64KB copy of g_WT)
    float* xs = sm + D * D;    // xs[m*XS_STRIDE + k]

    const int tid = threadIdx.x;
    const int m0  = blockIdx.x * BM;

    {
        const float4* src = (const float4*)g_WT;
        for (int lin = tid; lin < D * D / 4; lin += BLK_B)
            ((float4*)ws)[lin] = src[lin];
    }
    {
#pragma unroll
        for (int i = 0; i < (BM * D / 4) / BLK_B; i++) {   // 4 iters
            int lin = tid + i * BLK_B;
            int m   = lin >> 5;
            int k4  = lin & 31;
            int seg = m0 + m;
            float4 v = make_float4(0.f, 0.f, 0.f, 0.f);
            if (seg < NSEG) v = ((const float4*)g_sums)[seg * 32 + k4];
            *(float4*)(xs + m * XS_STRIDE + k4 * 4) = v;
        }
    }
    __syncthreads();

    const int tx = tid & 15;    // n-groups: [tx*4, +4) and [64+tx*4, +4)
    const int ty = tid >> 4;    // m-group: m = ty*2, ty*2+1  (ty 0..35)

    float acc[2][8];
#pragma unroll
    for (int i = 0; i < 2; i++)
#pragma unroll
        for (int j = 0; j < 8; j++) acc[i][j] = 0.f;

    const float* xp0 = xs + (ty * 2 + 0) * XS_STRIDE;
    const float* xp1 = xs + (ty * 2 + 1) * XS_STRIDE;
    const float* wp  = ws + tx * 4;

#pragma unroll 2
    for (int k = 0; k < D; k += 4) {
        float4 xv0 = *(const float4*)(xp0 + k);
        float4 xv1 = *(const float4*)(xp1 + k);
        const float xr[2][4] = {
            {xv0.x, xv0.y, xv0.z, xv0.w},
            {xv1.x, xv1.y, xv1.z, xv1.w},
        };
#pragma unroll
        for (int kk = 0; kk < 4; kk++) {
            float4 w0 = *(const float4*)(wp + (k + kk) * D);
            float4 w1 = *(const float4*)(wp + (k + kk) * D + 64);
#pragma unroll
            for (int i = 0; i < 2; i++) {
                float x = xr[i][kk];
                acc[i][0] += x * w0.x; acc[i][1] += x * w0.y;
                acc[i][2] += x * w0.z; acc[i][3] += x * w0.w;
                acc[i][4] += x * w1.x; acc[i][5] += x * w1.y;
                acc[i][6] += x * w1.z; acc[i][7] += x * w1.w;
            }
        }
    }

    float4 b0 = ((const float4*)b)[tx];
    float4 b1 = ((const float4*)b)[16 + tx];

    const bool is64 = graph_is64(graph);
#pragma unroll
    for (int i = 0; i < 2; i++) {
        int seg = m0 + ty * 2 + i;
        if (seg >= NSEG) continue;
        int st = seg_start(graph, is64, seg);
        int en = seg_end(graph, is64, seg);
        float cnt = (float)(en - st + 1);

        float4 o0, o1;
        o0.x = acc[i][0] + cnt * b0.x;
        o0.y = acc[i][1] + cnt * b0.y;
        o0.z = acc[i][2] + cnt * b0.z;
        o0.w = acc[i][3] + cnt * b0.w;
        o1.x = acc[i][4] + cnt * b1.x;
        o1.y = acc[i][5] + cnt * b1.y;
        o1.z = acc[i][6] + cnt * b1.z;
        o1.w = acc[i][7] + cnt * b1.w;

        float* op = out + (long long)seg * D;
        *(float4*)(op + tx * 4)      = o0;
        *(float4*)(op + 64 + tx * 4) = o1;
    }
}

extern "C" void kernel_launch(void* const* d_in, const int* in_sizes, int n_in,
                              void* d_out, int out_size) {
    const float* input = (const float*)d_in[0];
    const int*   graph = (const int*)  d_in[1];
    const float* W     = (const float*)d_in[2];
    const float* b     = (const float*)d_in[3];
    float*       out   = (float*)d_out;

    cudaFuncSetAttribute(seg_gemm_kernel,
                         cudaFuncAttributeMaxDynamicSharedMemorySize, SMEM_B);

    // Zero accumulator for the boundary-segment atomics (~0.7us memset node).
    void* sums_ptr = nullptr;
    cudaGetSymbolAddress(&sums_ptr, g_sums);
    cudaMemsetAsync(sums_ptr, 0, (size_t)NSEG * D * sizeof(float));

    sum_kernel<<<TBLK + NBLK_G, BLK_S>>>(input, graph, W);
    seg_gemm_kernel<<<NBLK_G, BLK_B, SMEM_B>>>(graph, b, out);
}